// round 3
// baseline (speedup 1.0000x reference)
#include <cuda_runtime.h>
#include <math.h>

#define EPS 1e-6f
#define MAXB 1024
#define MAXN 40000

__device__ __forceinline__ float fast_lg2(float x) {
    float r;
    asm("lg2.approx.f32 %0, %1;" : "=f"(r) : "f"(x));
    return r;
}
__device__ __forceinline__ float fast_ex2(float x) {
    float r;
    asm("ex2.approx.f32 %0, %1;" : "=f"(r) : "f"(x));
    return r;
}

// ---- scratch (static __device__ — no allocations allowed) ----
__device__ float g_ysq[MAXN];     // ||candidate||^2
__device__ float g_eb[MAXN];      // exp(bias)
__device__ float g_rowc[MAXB*8];  // per-query constants
__device__ float g_sumexp[MAXB];  // per-query sum of exp(logit)

// -------------------- init: zero accumulators --------------------
__global__ void hy_init(float* out, int B) {
    int i = blockIdx.x * blockDim.x + threadIdx.x;
    if (i < B) g_sumexp[i] = 0.f;
    if (i == 0) out[0] = 0.f;
}

// -------------------- prep candidates: y_sq, exp(bias) --------------------
__global__ void hy_prep_y(const float* __restrict__ C,
                          const float* __restrict__ bias, int N, int d) {
    int w = (blockIdx.x * blockDim.x + threadIdx.x) >> 5;
    int lane = threadIdx.x & 31;
    if (w >= N) return;
    const float* row = C + (long)w * d;
    float s = 0.f;
    for (int k = lane * 4; k < d; k += 128) {
        float4 v = *reinterpret_cast<const float4*>(row + k);
        s += v.x*v.x + v.y*v.y + v.z*v.z + v.w*v.w;
    }
    #pragma unroll
    for (int o = 16; o > 0; o >>= 1) s += __shfl_xor_sync(0xffffffffu, s, o);
    if (lane == 0) { g_ysq[w] = s; g_eb[w] = expf(bias[w]); }
}

// -------------------- prep queries: x_sq + derived constants --------------------
__global__ void hy_prep_x(const float* __restrict__ Q,
                          const float* __restrict__ curv, int B, int d) {
    int w = (blockIdx.x * blockDim.x + threadIdx.x) >> 5;
    int lane = threadIdx.x & 31;
    if (w >= B) return;
    const float* row = Q + (long)w * d;
    float s = 0.f;
    for (int k = lane * 4; k < d; k += 128) {
        float4 v = *reinterpret_cast<const float4*>(row + k);
        s += v.x*v.x + v.y*v.y + v.z*v.z + v.w*v.w;
    }
    #pragma unroll
    for (int o = 16; o > 0; o >>= 1) s += __shfl_xor_sync(0xffffffffu, s, o);
    if (lane == 0) {
        float c  = curv[w];
        float xs = s;
        float sc = sqrtf(c + EPS);
        float Bq = 1.f - c * xs;
        float* rc = g_rowc + w * 8;
        rc[0] = c;
        rc[1] = xs;
        rc[2] = Bq;
        rc[3] = Bq * Bq;
        rc[4] = c * c * xs;
        rc[5] = sc;
        rc[6] = -1.f / (sc + EPS);          // p : exp(-dist) = 2^(p*log2((1+z)/(1-z)))
        rc[7] = 1.f / (sc + EPS) - EPS;     // max_norm
    }
}

// -------------------- main fused GEMM + hyperbolic softmax-sum --------------------
// C_tile = Q[BM x d] . Cand[BN x d]^T, then per-element hyperbolic logit -> exp -> row sum
#define BM 128
#define BN 128
#define BK 16
#define TM 8
#define TN 8

__global__ __launch_bounds__(256)
void hy_gemm_fused(const float* __restrict__ Q, const float* __restrict__ C,
                   int B, int N, int d) {
    __shared__ float As[BK][BM];
    __shared__ float Bs[BK][BN];
    __shared__ float rc_s[BM][8];
    __shared__ float ysq_s[BN];
    __shared__ float eb_s[BN];

    const int tid = threadIdx.x;
    const int tx = tid & 15;          // 0..15 : column groups
    const int ty = tid >> 4;          // 0..15 : row groups
    const int m0 = blockIdx.y * BM;
    const int n0 = blockIdx.x * BN;

    // loader indices: 256 threads, each loads 2 float4 per tile per matrix
    const int rL = tid >> 2;          // 0..63
    const int cL = (tid & 3) * 4;     // k offset {0,4,8,12}

    float acc[TM][TN];
    #pragma unroll
    for (int i = 0; i < TM; i++)
        #pragma unroll
        for (int j = 0; j < TN; j++) acc[i][j] = 0.f;

    for (int kt = 0; kt < d; kt += BK) {
        // load A (queries) and B (candidates), transposed into smem [k][mn]
        #pragma unroll
        for (int r = 0; r < 2; r++) {
            int mrow = rL + r * 64;
            int gm = m0 + mrow;
            float4 va = make_float4(0.f, 0.f, 0.f, 0.f);
            if (gm < B)
                va = *reinterpret_cast<const float4*>(Q + (long)gm * d + kt + cL);
            As[cL+0][mrow] = va.x; As[cL+1][mrow] = va.y;
            As[cL+2][mrow] = va.z; As[cL+3][mrow] = va.w;

            int nrow = rL + r * 64;
            int gn = n0 + nrow;
            float4 vb = make_float4(0.f, 0.f, 0.f, 0.f);
            if (gn < N)
                vb = *reinterpret_cast<const float4*>(C + (long)gn * d + kt + cL);
            Bs[cL+0][nrow] = vb.x; Bs[cL+1][nrow] = vb.y;
            Bs[cL+2][nrow] = vb.z; Bs[cL+3][nrow] = vb.w;
        }
        __syncthreads();

        #pragma unroll
        for (int k = 0; k < BK; k++) {
            float af[TM], bf[TN];
            float4 a0 = *reinterpret_cast<const float4*>(&As[k][ty*TM]);
            float4 a1 = *reinterpret_cast<const float4*>(&As[k][ty*TM+4]);
            float4 b0 = *reinterpret_cast<const float4*>(&Bs[k][tx*TN]);
            float4 b1 = *reinterpret_cast<const float4*>(&Bs[k][tx*TN+4]);
            af[0]=a0.x; af[1]=a0.y; af[2]=a0.z; af[3]=a0.w;
            af[4]=a1.x; af[5]=a1.y; af[6]=a1.z; af[7]=a1.w;
            bf[0]=b0.x; bf[1]=b0.y; bf[2]=b0.z; bf[3]=b0.w;
            bf[4]=b1.x; bf[5]=b1.y; bf[6]=b1.z; bf[7]=b1.w;
            #pragma unroll
            for (int i = 0; i < TM; i++)
                #pragma unroll
                for (int j = 0; j < TN; j++)
                    acc[i][j] = fmaf(af[i], bf[j], acc[i][j]);
        }
        __syncthreads();
    }

    // stage per-row constants and per-col (y_sq, exp(bias)); zeros for OOB cols
    for (int idx = tid; idx < BM * 8; idx += 256) {
        int r = idx >> 3, c = idx & 7;
        int gm = m0 + r;
        rc_s[r][c] = (gm < B) ? g_rowc[gm * 8 + c] : 0.f;
    }
    for (int idx = tid; idx < BN; idx += 256) {
        int gn = n0 + idx;
        ysq_s[idx] = (gn < N) ? g_ysq[gn] : 0.f;   // OOB: u=0,v=0 -> finite, *eb=0
        eb_s[idx]  = (gn < N) ? g_eb[gn]  : 0.f;
    }
    __syncthreads();

    // epilogue: hyperbolic distance -> exp(logit), accumulate per-row sums
    #pragma unroll
    for (int i = 0; i < TM; i++) {
        int mrow = ty * TM + i;
        int gm = m0 + mrow;
        if (gm >= B) continue;
        const float c    = rc_s[mrow][0];
        const float xs   = rc_s[mrow][1];
        const float Bq   = rc_s[mrow][2];
        const float Bq2  = rc_s[mrow][3];
        const float c2xs = rc_s[mrow][4];
        const float sc   = rc_s[mrow][5];
        const float p    = rc_s[mrow][6];
        const float maxn = rc_s[mrow][7];
        const float m2c  = -2.f * c;
        const float m2Bq = -2.f * Bq;

        float rowsum = 0.f;
        #pragma unroll
        for (int j = 0; j < TN; j++) {
            float u = acc[i][j];
            float v = ysq_s[tx * TN + j];
            float t   = fmaf(-2.f, u, v);                  // v - 2u
            float A   = fmaf(c, t, 1.f);                   // 1 - 2cu + cv
            float den = fmaf(c2xs, v, fmaf(m2c, u, 1.f));  // 1 - 2cu + c^2 xs v
            float ns  = fmaf(Bq2, v, A * fmaf(m2Bq, u, A * xs));
            float r   = sqrtf(fmaxf(ns, 0.f));
            float dn  = __fdividef(r, den + EPS);
            dn = fminf(fmaxf(dn, EPS), maxn);
            float z = fminf(sc * dn, 1.f - EPS);
            // exp(-dist) = ((1-z)/(1+z))^(1/(sc+EPS)) = 2^(p*(log2(1+z)-log2(1-z)))
            float e = fast_ex2(p * (fast_lg2(1.f + z) - fast_lg2(1.f - z)));
            rowsum = fmaf(eb_s[tx * TN + j], e, rowsum);
        }
        // reduce across the 16 tx lanes sharing this row (stays in half-warp)
        #pragma unroll
        for (int o = 8; o > 0; o >>= 1)
            rowsum += __shfl_xor_sync(0xffffffffu, rowsum, o);
        if (tx == 0) atomicAdd(&g_sumexp[gm], rowsum);
    }
}

// -------------------- finalize: target logit, lse, mean --------------------
__global__ void hy_finalize(const float* __restrict__ Q, const float* __restrict__ C,
                            const float* __restrict__ bias, const int* __restrict__ tgt,
                            float* out, int B, int N, int d) {
    int w = (blockIdx.x * blockDim.x + threadIdx.x) >> 5;
    int lane = threadIdx.x & 31;
    if (w >= B) return;
    int t = tgt[w];
    const float* q  = Q + (long)w * d;
    const float* cd = C + (long)t * d;
    float s = 0.f;
    for (int k = lane * 4; k < d; k += 128) {
        float4 a = *reinterpret_cast<const float4*>(q + k);
        float4 b = *reinterpret_cast<const float4*>(cd + k);
        s += a.x*b.x + a.y*b.y + a.z*b.z + a.w*b.w;
    }
    #pragma unroll
    for (int o = 16; o > 0; o >>= 1) s += __shfl_xor_sync(0xffffffffu, s, o);
    if (lane == 0) {
        const float* rc = g_rowc + w * 8;
        float c = rc[0], xs = rc[1], Bq = rc[2], Bq2 = rc[3], c2xs = rc[4];
        float sc = rc[5], maxn = rc[7];
        float u = s, v = g_ysq[t];
        float tt  = fmaf(-2.f, u, v);
        float A   = fmaf(c, tt, 1.f);
        float den = fmaf(c2xs, v, fmaf(-2.f * c, u, 1.f));
        float ns  = fmaf(Bq2, v, A * fmaf(-2.f * Bq, u, A * xs));
        float r   = sqrtf(fmaxf(ns, 0.f));
        float dn  = r / (den + EPS);
        dn = fminf(fmaxf(dn, EPS), maxn);
        float z = fminf(sc * dn, 1.f - EPS);
        float dist = (2.f / (sc + EPS)) * atanhf(z);
        float tlogit = bias[t] - dist;
        float lse = logf(g_sumexp[w]);
        atomicAdd(out, (lse - tlogit) * (1.f / (float)B));
    }
}

// -------------------- launch --------------------
extern "C" void kernel_launch(void* const* d_in, const int* in_sizes, int n_in,
                              void* d_out, int out_size) {
    const float* Q    = (const float*)d_in[0];
    const float* C    = (const float*)d_in[1];
    const float* bias = (const float*)d_in[2];
    const float* curv = (const float*)d_in[3];
    const int*   tgt  = (const int*)d_in[4];
    float* out = (float*)d_out;

    int B = in_sizes[3];              // 1024 (curvature count)
    int N = in_sizes[2];              // 40000 (bias count)
    int d = in_sizes[0] / B;          // 512

    hy_init<<<(B + 255) / 256, 256>>>(out, B);
    hy_prep_y<<<(N * 32 + 255) / 256, 256>>>(C, bias, N, d);
    hy_prep_x<<<(B * 32 + 255) / 256, 256>>>(Q, curv, B, d);

    dim3 grid((N + BN - 1) / BN, (B + BM - 1) / BM);
    hy_gemm_fused<<<grid, 256>>>(Q, C, B, N, d);

    hy_finalize<<<(B * 32 + 255) / 256, 256>>>(Q, C, bias, tgt, out, B, N, d);
}

// round 5
// speedup vs baseline: 4.5716x; 4.5716x over previous
#include <cuda_runtime.h>
#include <cuda_bf16.h>
#include <math.h>
#include <stdint.h>

#define EPS 1e-6f
#define MAXB 1024
#define MAXN 40000
#define MAXD 512

// ===================== fast math =====================
__device__ __forceinline__ float fast_lg2(float x) {
    float r; asm("lg2.approx.f32 %0, %1;" : "=f"(r) : "f"(x)); return r;
}
__device__ __forceinline__ float fast_ex2(float x) {
    float r; asm("ex2.approx.f32 %0, %1;" : "=f"(r) : "f"(x)); return r;
}
__device__ __forceinline__ uint32_t smem_u32(const void* p) {
    uint32_t a;
    asm("{ .reg .u64 t; cvta.to.shared.u64 t, %1; cvt.u32.u64 %0, t; }" : "=r"(a) : "l"(p));
    return a;
}

// ===================== mma.sync helpers (arch-generic tensor path) =====================
#define LDSM_X4(r0, r1, r2, r3, addr)                                          \
    asm volatile("ldmatrix.sync.aligned.m8n8.x4.shared.b16 {%0,%1,%2,%3}, [%4];" \
        : "=r"(r0), "=r"(r1), "=r"(r2), "=r"(r3) : "r"(addr))

#define MMA16816(c, a, b0, b1)                                                 \
    asm volatile("mma.sync.aligned.m16n8k16.row.col.f32.bf16.bf16.f32 "        \
        "{%0,%1,%2,%3}, {%4,%5,%6,%7}, {%8,%9}, {%0,%1,%2,%3};"                \
        : "+f"((c)[0]), "+f"((c)[1]), "+f"((c)[2]), "+f"((c)[3])               \
        : "r"((a)[0]), "r"((a)[1]), "r"((a)[2]), "r"((a)[3]), "r"(b0), "r"(b1))

__device__ __forceinline__ void cp16(uint32_t dst, const void* src, bool pred) {
    int sz = pred ? 16 : 0;
    asm volatile("cp.async.cg.shared.global [%0], [%1], 16, %2;"
        :: "r"(dst), "l"(src), "r"(sz) : "memory");
}
#define CP_COMMIT() asm volatile("cp.async.commit_group;" ::: "memory")
#define CP_WAIT(n)  asm volatile("cp.async.wait_group %0;" :: "n"(n) : "memory")

// ===================== scratch (__device__ globals; no allocs) =====================
__device__ __align__(16) __nv_bfloat16 g_Qb[MAXB * MAXD];
__device__ __align__(16) __nv_bfloat16 g_Cb[MAXN * MAXD];
__device__ float g_ysq[MAXN];
__device__ float g_eb[MAXN];
__device__ float g_rowc[MAXB * 8];
__device__ float g_sumexp[MAXB];

// ===================== init =====================
__global__ void hy_init(float* out, int B) {
    int i = blockIdx.x * blockDim.x + threadIdx.x;
    if (i < B) g_sumexp[i] = 0.f;
    if (i == 0) out[0] = 0.f;
}

// ===================== prep candidates =====================
__global__ void hy_prep_y(const float* __restrict__ C,
                          const float* __restrict__ bias, int N, int d) {
    int w = (blockIdx.x * blockDim.x + threadIdx.x) >> 5;
    int lane = threadIdx.x & 31;
    if (w >= N) return;
    const float* row = C + (long)w * d;
    __nv_bfloat16* brow = g_Cb + (long)w * d;
    float s = 0.f;
    for (int k = lane * 4; k < d; k += 128) {
        float4 v = *reinterpret_cast<const float4*>(row + k);
        s += v.x*v.x + v.y*v.y + v.z*v.z + v.w*v.w;
        __nv_bfloat162* bp = reinterpret_cast<__nv_bfloat162*>(brow + k);
        bp[0] = __floats2bfloat162_rn(v.x, v.y);
        bp[1] = __floats2bfloat162_rn(v.z, v.w);
    }
    #pragma unroll
    for (int o = 16; o > 0; o >>= 1) s += __shfl_xor_sync(0xffffffffu, s, o);
    if (lane == 0) { g_ysq[w] = s; g_eb[w] = expf(bias[w]); }
}

// ===================== prep queries =====================
__global__ void hy_prep_x(const float* __restrict__ Q,
                          const float* __restrict__ curv, int B, int d) {
    int w = (blockIdx.x * blockDim.x + threadIdx.x) >> 5;
    int lane = threadIdx.x & 31;
    if (w >= B) return;
    const float* row = Q + (long)w * d;
    __nv_bfloat16* brow = g_Qb + (long)w * d;
    float s = 0.f;
    for (int k = lane * 4; k < d; k += 128) {
        float4 v = *reinterpret_cast<const float4*>(row + k);
        s += v.x*v.x + v.y*v.y + v.z*v.z + v.w*v.w;
        __nv_bfloat162* bp = reinterpret_cast<__nv_bfloat162*>(brow + k);
        bp[0] = __floats2bfloat162_rn(v.x, v.y);
        bp[1] = __floats2bfloat162_rn(v.z, v.w);
    }
    #pragma unroll
    for (int o = 16; o > 0; o >>= 1) s += __shfl_xor_sync(0xffffffffu, s, o);
    if (lane == 0) {
        float c  = curv[w];
        float xs = s;
        float sc = sqrtf(c + EPS);
        float Bq = 1.f - c * xs;
        float* rc = g_rowc + w * 8;
        rc[0] = c;  rc[1] = xs;  rc[2] = Bq;  rc[3] = Bq * Bq;
        rc[4] = c * c * xs;  rc[5] = sc;
        rc[6] = -1.f / (sc + EPS);
        rc[7] = 1.f / (sc + EPS) - EPS;
    }
}

// ===================== main HMMA fused kernel =====================
#define BM 128
#define BN 128
#define BK 32
#define RSB 80            // padded row stride in bytes (40 bf16)
#define TILE_B (BM * RSB) // 10240 bytes per tile buffer

__global__ __launch_bounds__(256)
void hy_mma(int B, int N, int d) {
    __shared__ __align__(16) char smA[2][TILE_B];
    __shared__ __align__(16) char smB[2][TILE_B];
    __shared__ float rc_s[BM][8];
    __shared__ float ysq_s[BN];
    __shared__ float eb_s[BN];

    const int tid = threadIdx.x;
    const int wid = tid >> 5;
    const int lane = tid & 31;
    const int m0 = blockIdx.y * BM;
    const int n0 = blockIdx.x * BN;
    const int NKT = d / BK;

    const uint32_t sA0 = smem_u32(&smA[0][0]);
    const uint32_t sA1 = smem_u32(&smA[1][0]);
    const uint32_t sB0 = smem_u32(&smB[0][0]);
    const uint32_t sB1 = smem_u32(&smB[1][0]);

    // stage epilogue constants
    for (int idx = tid; idx < BM * 8; idx += 256) {
        int r = idx >> 3, cc = idx & 7, gm = m0 + r;
        rc_s[r][cc] = (gm < B) ? g_rowc[gm * 8 + cc] : 0.f;
    }
    for (int idx = tid; idx < BN; idx += 256) {
        int gn = n0 + idx;
        ysq_s[idx] = (gn < N) ? g_ysq[gn] : 0.f;
        eb_s[idx]  = (gn < N) ? g_eb[gn]  : 0.f;
    }

    // loader geometry: 512 16B chunks per tile, 2 per thread
    const int lrow = tid >> 2;          // 0..63  (+64 for second)
    const int lc16 = tid & 3;           // 16B column

    // ---- prefetch k-chunk 0 ----
    {
        #pragma unroll
        for (int i = 0; i < 2; i++) {
            int row = lrow + i * 64;
            int gm = m0 + row;
            bool ok = gm < B;
            cp16(sA0 + row * RSB + lc16 * 16,
                 g_Qb + ((long)(ok ? gm : 0) * d + lc16 * 8), ok);
        }
        #pragma unroll
        for (int i = 0; i < 2; i++) {
            int row = lrow + i * 64;
            int gn = n0 + row;
            bool ok = gn < N;
            cp16(sB0 + row * RSB + lc16 * 16,
                 g_Cb + ((long)(ok ? gn : 0) * d + lc16 * 8), ok);
        }
        CP_COMMIT();
    }

    // warp tile: 32 (m) x 64 (n)
    const int wm = (wid & 3) * 32;
    const int wn = (wid >> 2) * 64;
    // ldmatrix base addresses (buffer 0; buffer 1 = +off)
    const uint32_t aoff = sA1 - sA0;
    const uint32_t boff = sB1 - sB0;
    const uint32_t a_base = sA0 + (wm + (lane & 15)) * RSB + (lane >> 4) * 16;
    const uint32_t b_base = sB0 + (wn + (lane >> 4) * 8 + (lane & 7)) * RSB + ((lane >> 3) & 1) * 16;

    float acc[2][8][4];
    #pragma unroll
    for (int mi = 0; mi < 2; mi++)
        #pragma unroll
        for (int ni = 0; ni < 8; ni++)
            #pragma unroll
            for (int q = 0; q < 4; q++) acc[mi][ni][q] = 0.f;

    for (int kt = 0; kt < NKT; kt++) {
        const uint32_t abuf = (kt & 1) ? aoff : 0;
        const uint32_t bbuf = (kt & 1) ? boff : 0;

        if (kt + 1 < NKT) {
            const uint32_t na = ((kt + 1) & 1) ? aoff : 0;
            const uint32_t nb = ((kt + 1) & 1) ? boff : 0;
            #pragma unroll
            for (int i = 0; i < 2; i++) {
                int row = lrow + i * 64;
                int gm = m0 + row;
                bool ok = gm < B;
                cp16(sA0 + na + row * RSB + lc16 * 16,
                     g_Qb + ((long)(ok ? gm : 0) * d + (kt + 1) * BK + lc16 * 8), ok);
            }
            #pragma unroll
            for (int i = 0; i < 2; i++) {
                int row = lrow + i * 64;
                int gn = n0 + row;
                bool ok = gn < N;
                cp16(sB0 + nb + row * RSB + lc16 * 16,
                     g_Cb + ((long)(ok ? gn : 0) * d + (kt + 1) * BK + lc16 * 8), ok);
            }
            CP_COMMIT();
            CP_WAIT(1);
        } else {
            CP_WAIT(0);
        }
        __syncthreads();

        #pragma unroll
        for (int ks = 0; ks < 2; ks++) {
            uint32_t a[2][4];
            #pragma unroll
            for (int mi = 0; mi < 2; mi++)
                LDSM_X4(a[mi][0], a[mi][1], a[mi][2], a[mi][3],
                        a_base + abuf + mi * 16 * RSB + ks * 32);
            uint32_t b[4][4];   // [g][0,1]=n-tile 2g ; [g][2,3]=n-tile 2g+1
            #pragma unroll
            for (int g = 0; g < 4; g++)
                LDSM_X4(b[g][0], b[g][1], b[g][2], b[g][3],
                        b_base + bbuf + g * 16 * RSB + ks * 32);
            #pragma unroll
            for (int mi = 0; mi < 2; mi++)
                #pragma unroll
                for (int ni = 0; ni < 8; ni++)
                    MMA16816(acc[mi][ni], a[mi], b[ni >> 1][(ni & 1) * 2],
                             b[ni >> 1][(ni & 1) * 2 + 1]);
        }
        __syncthreads();
    }

    // ---------------- epilogue ----------------
    #pragma unroll
    for (int mi = 0; mi < 2; mi++) {
        #pragma unroll
        for (int half = 0; half < 2; half++) {
            const int mrow = wm + mi * 16 + half * 8 + (lane >> 2);
            const int gm = m0 + mrow;
            const float c    = rc_s[mrow][0];
            const float xs   = rc_s[mrow][1];
            const float Bq   = rc_s[mrow][2];
            const float Bq2  = rc_s[mrow][3];
            const float c2xs = rc_s[mrow][4];
            const float sc   = rc_s[mrow][5];
            const float p    = rc_s[mrow][6];
            const float maxn = rc_s[mrow][7];
            const float m2c  = -2.f * c;
            const float m2Bq = -2.f * Bq;

            float rowsum = 0.f;
            #pragma unroll
            for (int ni = 0; ni < 8; ni++) {
                #pragma unroll
                for (int q = 0; q < 2; q++) {
                    float u  = acc[mi][ni][half * 2 + q];
                    int col  = wn + ni * 8 + 2 * (lane & 3) + q;
                    float v  = ysq_s[col];
                    float eb = eb_s[col];
                    float t    = fmaf(-2.f, u, v);
                    float A    = fmaf(c, t, 1.f);
                    float denp = fmaf(c2xs, v, fmaf(m2c, u, 1.f)) + EPS;
                    float ns   = fmaf(Bq2, v, A * fmaf(m2Bq, u, A * xs));
                    float r0   = sqrtf(fmaxf(ns, 0.f));
                    r0 = fminf(fmaxf(r0, EPS * denp), maxn * denp);
                    float s    = sc * r0;
                    float ratio = __fdividef(denp + s, denp - s);   // (1+z)/(1-z)
                    rowsum = fmaf(eb, fast_ex2(p * fast_lg2(ratio)), rowsum);
                }
            }
            rowsum += __shfl_xor_sync(0xffffffffu, rowsum, 1);
            rowsum += __shfl_xor_sync(0xffffffffu, rowsum, 2);
            if ((lane & 3) == 0 && gm < B) atomicAdd(&g_sumexp[gm], rowsum);
        }
    }
}

// ===================== finalize =====================
__global__ void hy_finalize(const float* __restrict__ Q, const float* __restrict__ C,
                            const float* __restrict__ bias, const int* __restrict__ tgt,
                            float* out, int B, int N, int d) {
    int w = (blockIdx.x * blockDim.x + threadIdx.x) >> 5;
    int lane = threadIdx.x & 31;
    if (w >= B) return;
    int t = tgt[w];
    const float* q  = Q + (long)w * d;
    const float* cd = C + (long)t * d;
    float s = 0.f;
    for (int k = lane * 4; k < d; k += 128) {
        float4 a = *reinterpret_cast<const float4*>(q + k);
        float4 b = *reinterpret_cast<const float4*>(cd + k);
        s += a.x*b.x + a.y*b.y + a.z*b.z + a.w*b.w;
    }
    #pragma unroll
    for (int o = 16; o > 0; o >>= 1) s += __shfl_xor_sync(0xffffffffu, s, o);
    if (lane == 0) {
        const float* rc = g_rowc + w * 8;
        float c = rc[0], xs = rc[1], Bq = rc[2], Bq2 = rc[3], c2xs = rc[4];
        float sc = rc[5], maxn = rc[7];
        float u = s, v = g_ysq[t];
        float tt  = fmaf(-2.f, u, v);
        float A   = fmaf(c, tt, 1.f);
        float den = fmaf(c2xs, v, fmaf(-2.f * c, u, 1.f));
        float ns  = fmaf(Bq2, v, A * fmaf(-2.f * Bq, u, A * xs));
        float r   = sqrtf(fmaxf(ns, 0.f));
        float dn  = r / (den + EPS);
        dn = fminf(fmaxf(dn, EPS), maxn);
        float z = fminf(sc * dn, 1.f - EPS);
        float dist = (2.f / (sc + EPS)) * atanhf(z);
        float tlogit = bias[t] - dist;
        float lse = logf(g_sumexp[w]);
        atomicAdd(out, (lse - tlogit) * (1.f / (float)B));
    }
}

// ===================== launch =====================
extern "C" void kernel_launch(void* const* d_in, const int* in_sizes, int n_in,
                              void* d_out, int out_size) {
    const float* Q    = (const float*)d_in[0];
    const float* C    = (const float*)d_in[1];
    const float* bias = (const float*)d_in[2];
    const float* curv = (const float*)d_in[3];
    const int*   tgt  = (const int*)d_in[4];
    float* out = (float*)d_out;

    int B = in_sizes[3];
    int N = in_sizes[2];
    int d = in_sizes[0] / B;

    hy_init<<<(B + 255) / 256, 256>>>(out, B);
    hy_prep_y<<<(N * 32 + 255) / 256, 256>>>(C, bias, N, d);
    hy_prep_x<<<(B * 32 + 255) / 256, 256>>>(Q, curv, B, d);

    dim3 grid((N + BN - 1) / BN, (B + BM - 1) / BM);
    hy_mma<<<grid, 256>>>(B, N, d);

    hy_finalize<<<(B * 32 + 255) / 256, 256>>>(Q, C, bias, tgt, out, B, N, d);
}